// round 3
// baseline (speedup 1.0000x reference)
#include <cuda_runtime.h>
#include <math.h>

#define N_NODESC 20000
#define N_EDGESC 640000
#define FEATC    128
#define N_RBFC   20
#define CUTOFFC  5.0f
#define PIF      3.14159265358979323846f

// ---------------- scratch (__device__ globals; no allocation) ----------------
__device__ __align__(16) float g_phi[N_NODESC * 3 * FEATC];   // phi_node, [N,384]
__device__ __align__(16) int   g_count[N_NODESC];
__device__ __align__(16) int   g_cursor[N_NODESC];
__device__ __align__(16) int   g_rowptr[N_NODESC + 1];
__device__ __align__(16) int   g_eid[N_EDGESC];
__device__ __align__(16) int   g_src[N_EDGESC];
__device__ __align__(16) int   g_dst[N_EDGESC];
__device__ int g_flag;   // 0 -> nbrs is int64, nonzero -> int32

// ---------------- zero counters ----------------
__global__ void zero_kernel() {
    int i = blockIdx.x * blockDim.x + threadIdx.x;
    if (i < N_NODESC) { g_count[i] = 0; g_cursor[i] = 0; }
    if (i == 0) g_flag = 0;
}

// ---------------- dtype probe ----------------
// If nbrs is int64 (values in [0,20000), non-negative) every odd 32-bit word
// is the zero high-half. If int32, odd words are random j indices.
__global__ void detect_kernel(const int* __restrict__ nbrs32) {
    int t = threadIdx.x;                 // 1024 threads, one block
    int v = nbrs32[2 * t + 1];           // indices < 2048 < 2*N_EDGES: safe either way
    __shared__ int red[1024];
    red[t] = v;
    __syncthreads();
    for (int off = 512; off > 0; off >>= 1) {
        if (t < off) red[t] |= red[t + off];
        __syncthreads();
    }
    if (t == 0) g_flag = red[0];
}

// ---------------- normalize indices to int32 SoA ----------------
__global__ void extract_kernel(const void* __restrict__ nbrs) {
    int e = blockIdx.x * blockDim.x + threadIdx.x;
    if (e >= N_EDGESC) return;
    if (g_flag != 0) {   // int32 storage
        const int* p = (const int*)nbrs;
        g_src[e] = p[2 * e];
        g_dst[e] = p[2 * e + 1];
    } else {             // int64 storage
        const long long* p = (const long long*)nbrs;
        g_src[e] = (int)p[2 * (long long)e];
        g_dst[e] = (int)p[2 * (long long)e + 1];
    }
}

// ---------------- fused node MLP: phi = silu(s@W1+b1)@W2 + b2 ----------------
__global__ __launch_bounds__(256) void phi_kernel(
    const float* __restrict__ s,
    const float* __restrict__ W1, const float* __restrict__ b1,
    const float* __restrict__ W2, const float* __restrict__ b2)
{
    __shared__ __align__(16) float s_sm[32][FEATC];
    __shared__ __align__(16) float h_sm[32][FEATC];
    int tid = threadIdx.x;
    int node0 = blockIdx.x * 32;

    const float4* s4 = reinterpret_cast<const float4*>(s + (size_t)node0 * FEATC);
    float4* ssm4 = reinterpret_cast<float4*>(&s_sm[0][0]);
    for (int idx = tid; idx < 32 * FEATC / 4; idx += 256) ssm4[idx] = s4[idx];
    __syncthreads();

    int cx = tid & 31;   // col group: cols 4cx..4cx+3
    int ny = tid >> 5;   // node group: nodes 4ny..4ny+3

    // stage 1: h = silu(s@W1 + b1)
    {
        float acc[4][4];
        #pragma unroll
        for (int i = 0; i < 4; i++)
            #pragma unroll
            for (int j = 0; j < 4; j++) acc[i][j] = 0.0f;
        const float4* W1v = reinterpret_cast<const float4*>(W1);
        #pragma unroll 8
        for (int k = 0; k < FEATC; k++) {
            float4 w = W1v[k * 32 + cx];
            #pragma unroll
            for (int i = 0; i < 4; i++) {
                float a = s_sm[ny * 4 + i][k];
                acc[i][0] += a * w.x; acc[i][1] += a * w.y;
                acc[i][2] += a * w.z; acc[i][3] += a * w.w;
            }
        }
        float4 bb = reinterpret_cast<const float4*>(b1)[cx];
        #pragma unroll
        for (int i = 0; i < 4; i++) {
            float x0 = acc[i][0] + bb.x, x1 = acc[i][1] + bb.y;
            float x2 = acc[i][2] + bb.z, x3 = acc[i][3] + bb.w;
            float4 h;
            h.x = x0 / (1.0f + expf(-x0));
            h.y = x1 / (1.0f + expf(-x1));
            h.z = x2 / (1.0f + expf(-x2));
            h.w = x3 / (1.0f + expf(-x3));
            *reinterpret_cast<float4*>(&h_sm[ny * 4 + i][cx * 4]) = h;
        }
    }
    __syncthreads();

    // stage 2: phi = h@W2 + b2  (3 groups of 128 output cols)
    const float4* W2v = reinterpret_cast<const float4*>(W2);   // row = 96 float4
    for (int g = 0; g < 3; g++) {
        float acc[4][4];
        #pragma unroll
        for (int i = 0; i < 4; i++)
            #pragma unroll
            for (int j = 0; j < 4; j++) acc[i][j] = 0.0f;
        #pragma unroll 8
        for (int k = 0; k < FEATC; k++) {
            float4 w = W2v[k * 96 + g * 32 + cx];
            #pragma unroll
            for (int i = 0; i < 4; i++) {
                float a = h_sm[ny * 4 + i][k];
                acc[i][0] += a * w.x; acc[i][1] += a * w.y;
                acc[i][2] += a * w.z; acc[i][3] += a * w.w;
            }
        }
        float4 bb = reinterpret_cast<const float4*>(b2)[g * 32 + cx];
        #pragma unroll
        for (int i = 0; i < 4; i++) {
            float4 o;
            o.x = acc[i][0] + bb.x; o.y = acc[i][1] + bb.y;
            o.z = acc[i][2] + bb.z; o.w = acc[i][3] + bb.w;
            *reinterpret_cast<float4*>(
                &g_phi[(size_t)(node0 + ny * 4 + i) * 384 + g * 128 + cx * 4]) = o;
        }
    }
}

// ---------------- CSR build ----------------
__global__ void count_kernel() {
    int e = blockIdx.x * blockDim.x + threadIdx.x;
    if (e < N_EDGESC) atomicAdd(&g_count[g_src[e]], 1);
}

__global__ void scan_kernel() {
    __shared__ int sm[1024];
    __shared__ int carry_sm;
    int t = threadIdx.x;
    if (t == 0) carry_sm = 0;
    __syncthreads();
    for (int base = 0; base < N_NODESC; base += 1024) {
        int idx = base + t;
        int v = (idx < N_NODESC) ? g_count[idx] : 0;
        int x = v;
        sm[t] = x;
        __syncthreads();
        for (int off = 1; off < 1024; off <<= 1) {
            int y = (t >= off) ? sm[t - off] : 0;
            __syncthreads();
            x += y;
            sm[t] = x;
            __syncthreads();
        }
        int carry = carry_sm;
        if (idx < N_NODESC) g_rowptr[idx] = carry + x - v;   // exclusive
        __syncthreads();
        if (t == 1023) carry_sm = carry + x;
        __syncthreads();
    }
    if (t == 0) g_rowptr[N_NODESC] = carry_sm;
}

__global__ void scatter_kernel() {
    int e = blockIdx.x * blockDim.x + threadIdx.x;
    if (e < N_EDGESC) {
        int i = g_src[e];
        int pos = g_rowptr[i] + atomicAdd(&g_cursor[i], 1);
        g_eid[pos] = e;
    }
}

// ---------------- node-parallel accumulate ----------------
#define STAGE 64
__global__ __launch_bounds__(128, 4) void accum_kernel(
    const float* __restrict__ v_j, const float* __restrict__ r_ij,
    const float* __restrict__ Wd, const float* __restrict__ bd,
    float* __restrict__ out_s, float* __restrict__ out_v)
{
    __shared__ __align__(16) float sm_g[STAGE][N_RBFC + 1];   // pad -> conflict-free
    __shared__ __align__(16) float sm_unit[STAGE][3];
    __shared__ __align__(16) float sm_env[STAGE];
    __shared__ __align__(16) int   sm_j[STAGE];

    int f = threadIdx.x;   // feature 0..127

    float wd0[N_RBFC], wd1[N_RBFC], wd2[N_RBFC];
    #pragma unroll
    for (int k = 0; k < N_RBFC; k++) {
        wd0[k] = Wd[k * 384 + f];
        wd1[k] = Wd[k * 384 + 128 + f];
        wd2[k] = Wd[k * 384 + 256 + f];
    }
    float bd0 = bd[f], bd1 = bd[128 + f], bd2 = bd[256 + f];

    for (int node = blockIdx.x; node < N_NODESC; node += gridDim.x) {
        int start = g_rowptr[node];
        int end   = g_rowptr[node + 1];
        float accs = 0.0f, av0 = 0.0f, av1 = 0.0f, av2 = 0.0f;

        for (int base = start; base < end; base += STAGE) {
            int n = end - base; if (n > STAGE) n = STAGE;
            __syncthreads();
            // phase A: stage per-edge geometry / RBF (one thread per edge)
            if (f < n) {
                int eid = g_eid[base + f];
                float r0 = r_ij[3 * (size_t)eid + 0];
                float r1 = r_ij[3 * (size_t)eid + 1];
                float r2 = r_ij[3 * (size_t)eid + 2];
                float d2 = r0 * r0 + r1 * r1 + r2 * r2 + 3e-15f;
                float d  = sqrtf(d2);
                float rinv = 1.0f / d;
                sm_unit[f][0] = r0 * rinv;
                sm_unit[f][1] = r1 * rinv;
                sm_unit[f][2] = r2 * rinv;
                float x = (PIF / CUTOFFC) * d;
                float sx = sinf(x), cxx = cosf(x);
                float env = (d < CUTOFFC) ? 0.5f * (cxx + 1.0f) : 0.0f;
                sm_env[f] = env;
                float scale = env * rinv;
                float twoc = 2.0f * cxx;
                float sp = 0.0f, sc = sx;  // sin(k*x) Chebyshev recurrence
                #pragma unroll
                for (int k = 0; k < N_RBFC; k++) {
                    sm_g[f][k] = sc * scale;
                    float sn = twoc * sc - sp;
                    sp = sc; sc = sn;
                }
                sm_j[f] = g_dst[eid];
            }
            __syncthreads();
            // phase B: all 128 threads accumulate this batch of edges
            for (int t2 = 0; t2 < n; t2++) {
                int j = sm_j[t2];
                const float* ph = g_phi + (size_t)j * 384;
                float phi0 = ph[f], phi1 = ph[128 + f], phi2 = ph[256 + f];
                const float* vv = v_j + (size_t)j * 384 + 3 * f;
                float vx = vv[0], vy = vv[1], vz = vv[2];
                float tenv = sm_env[t2];
                float ws0 = bd0 * tenv, ws1 = bd1 * tenv, ws2 = bd2 * tenv;
                #pragma unroll
                for (int k = 0; k < N_RBFC; k++) {
                    float g = sm_g[t2][k];
                    ws0 += g * wd0[k];
                    ws1 += g * wd1[k];
                    ws2 += g * wd2[k];
                }
                float i0 = phi0 * ws0;
                float i1 = phi1 * ws1;
                float i2 = phi2 * ws2;
                accs += i1;
                float u0 = sm_unit[t2][0], u1 = sm_unit[t2][1], u2 = sm_unit[t2][2];
                av0 += i2 * u0; av0 += i0 * vx;
                av1 += i2 * u1; av1 += i0 * vy;
                av2 += i2 * u2; av2 += i0 * vz;
            }
        }
        out_s[(size_t)node * FEATC + f] = accs;
        float* ov = out_v + (size_t)node * 384 + 3 * f;
        ov[0] = av0; ov[1] = av1; ov[2] = av2;
    }
}

// ---------------- launch ----------------
extern "C" void kernel_launch(void* const* d_in, const int* in_sizes, int n_in,
                              void* d_out, int out_size) {
    (void)in_sizes; (void)n_in; (void)out_size;
    const float* s_j  = (const float*)d_in[0];
    const float* v_j  = (const float*)d_in[1];
    const float* r_ij = (const float*)d_in[2];
    const void*  nbrs = d_in[3];
    const float* W1   = (const float*)d_in[4];
    const float* b1   = (const float*)d_in[5];
    const float* W2   = (const float*)d_in[6];
    const float* b2   = (const float*)d_in[7];
    const float* Wd   = (const float*)d_in[8];
    const float* bd   = (const float*)d_in[9];
    float* out   = (float*)d_out;
    float* out_s = out;                              // [N,128]
    float* out_v = out + (size_t)N_NODESC * FEATC;   // [N,128,3]

    zero_kernel<<<(N_NODESC + 255) / 256, 256>>>();
    detect_kernel<<<1, 1024>>>((const int*)nbrs);
    extract_kernel<<<(N_EDGESC + 255) / 256, 256>>>(nbrs);
    phi_kernel<<<N_NODESC / 32, 256>>>(s_j, W1, b1, W2, b2);
    count_kernel<<<(N_EDGESC + 255) / 256, 256>>>();
    scan_kernel<<<1, 1024>>>();
    scatter_kernel<<<(N_EDGESC + 255) / 256, 256>>>();
    accum_kernel<<<1184, 128>>>(v_j, r_ij, Wd, bd, out_s, out_v);
}